// round 14
// baseline (speedup 1.0000x reference)
#include <cuda_runtime.h>
#include <cuda_fp16.h>
#include <math.h>
#include <stdint.h>

#define T_STEPS 64
#define BATCH   1024
#define HID     512
#define VOCAB   512
#define G4H     2048

typedef unsigned long long u64;

// ---------------------------------------------------------------------------
// Device-global scratch (allocation-free)
// A-side operands (h, emb) pre-scaled by 16; B-side weights by 32.
// GEMM accumulators therefore carry 512x; epilogues multiply by 1/512.
// ---------------------------------------------------------------------------
__device__ float  g_c[BATCH * HID];            // cell state fp32
__device__ __half g_hs[2][2][BATCH * HID];     // 16*h 2-way fp16 splits, ping-pong
__device__ __half g_Wih[2][G4H * HID];         // 32*W_ih splits (gate-interleaved)
__device__ __half g_Whh[2][G4H * HID];         // 32*W_hh splits (gate-interleaved)
__device__ __half g_Wo[2][VOCAB * HID];        // 32*W_out splits
__device__ __half g_emb[2][VOCAB * HID];       // 16*embedding splits
__device__ float  g_bias[G4H];                 // gate-interleaved b_ih+b_hh
__device__ float  g_E[VOCAB * G4H];            // emb @ W_ih^T + bias (fp32, true scale)
__device__ u64    g_amax[2][BATCH];            // packed (mapped logit, 511-col)

#define INV512 (1.0f / 512.0f)

// ---------------------------------------------------------------------------
// Helpers
// ---------------------------------------------------------------------------
__device__ __forceinline__ uint32_t smem_u32(const void* p) {
    uint32_t a;
    asm("{ .reg .u64 t; cvta.to.shared.u64 t, %1; cvt.u32.u64 %0, t; }"
        : "=r"(a) : "l"(p));
    return a;
}

#define SWZ(x) ((x) ^ (((x) >> 3) & 0x70))

__device__ __forceinline__ void cp16(uint32_t dst, const void* src) {
    asm volatile("cp.async.cg.shared.global [%0], [%1], 16;" :: "r"(dst), "l"(src));
}

__device__ __forceinline__ void ldsm4(uint32_t& r0, uint32_t& r1,
                                      uint32_t& r2, uint32_t& r3, uint32_t addr) {
    asm volatile("ldmatrix.sync.aligned.m8n8.x4.shared.b16 {%0,%1,%2,%3}, [%4];"
                 : "=r"(r0), "=r"(r1), "=r"(r2), "=r"(r3) : "r"(addr));
}

__device__ __forceinline__ void mma_f16(float c[4], const uint32_t a[4],
                                        const uint32_t b[2]) {
    asm volatile(
        "mma.sync.aligned.m16n8k16.row.col.f32.f16.f16.f32 "
        "{%0,%1,%2,%3}, {%4,%5,%6,%7}, {%8,%9}, {%0,%1,%2,%3};"
        : "+f"(c[0]), "+f"(c[1]), "+f"(c[2]), "+f"(c[3])
        : "r"(a[0]), "r"(a[1]), "r"(a[2]), "r"(a[3]), "r"(b[0]), "r"(b[1]));
}

// Exact 2-way fp16 split of a pre-scaled value
__device__ __forceinline__ void split2(float v, __half& s0, __half& s1) {
    s0 = __float2half_rn(v);
    s1 = __float2half_rn(v - __half2float(s0));
}

// Monotone float->u32 map; key packs (value, 511-col) for first-max argmax
__device__ __forceinline__ u64 amax_key(float v, int col) {
    uint32_t u = __float_as_uint(v);
    uint32_t mu = (u & 0x80000000u) ? ~u : (u | 0x80000000u);
    return ((u64)mu << 32) | (uint32_t)(511 - col);
}

// ---------------------------------------------------------------------------
// Prep kernels
// ---------------------------------------------------------------------------
__global__ void prep_gates(const float* __restrict__ Wih, const float* __restrict__ Whh,
                           const float* __restrict__ bih, const float* __restrict__ bhh) {
    int idx = blockIdx.x * blockDim.x + threadIdx.x;    // [0, G4H*HID)
    int n = idx >> 9;
    int k = idx & 511;
    int orig = ((n & 3) << 9) + (n >> 2);               // interleave i,f,g,o per j
    split2(32.0f * Wih[(size_t)orig * 512 + k], g_Wih[0][idx], g_Wih[1][idx]);
    split2(32.0f * Whh[(size_t)orig * 512 + k], g_Whh[0][idx], g_Whh[1][idx]);
    if (k == 0) g_bias[n] = bih[orig] + bhh[orig];
}

__global__ void prep_out(const float* __restrict__ Wout, const float* __restrict__ emb) {
    int idx = blockIdx.x * blockDim.x + threadIdx.x;    // [0, VOCAB*HID)
    split2(32.0f * Wout[idx], g_Wo[0][idx], g_Wo[1][idx]);
    split2(16.0f * emb[idx], g_emb[0][idx], g_emb[1][idx]);
}

__global__ void init_state_tc(const float* __restrict__ ench,
                              const float* __restrict__ encc) {
    int idx = blockIdx.x * blockDim.x + threadIdx.x;    // [0, BATCH*HID)
    g_c[idx] = encc[idx];
    split2(16.0f * ench[idx], g_hs[0][0][idx], g_hs[0][1][idx]);
    if ((idx & 511) == 0) g_amax[1][idx >> 9] = 511ull;  // decodes to SOS token 0
}

// ---------------------------------------------------------------------------
// 128x128 main loop (K=512 in 8 chunks of 64), 256 threads, 8 warps (2Mx4N)
// Warp tile 64x32.  smem: double buffer of 4 tiles x 16KB (2 A splits, 2 B).
// Split products (0,0),(0,1),(1,0); one A-split live at a time.
// (Round-12-proven configuration.)
// ---------------------------------------------------------------------------
#define TILE128   16384
#define BUF128    (4 * TILE128)        // 65536
#define SMEM128   (2 * BUF128 + 1024)

__device__ __forceinline__ void load128(uint32_t bufb, int tid,
                                        const __half* const srcs[4], int koff) {
#pragma unroll
    for (int i = 0; i < 16; i++) {
        int t = i >> 2;
        int u = tid + (i & 3) * 256;
        int row = u >> 3;
        int cb = u & 7;
        cp16(bufb + (t << 14) + SWZ(row * 128 + cb * 16),
             srcs[t] + (size_t)row * 512 + koff + cb * 8);
    }
    asm volatile("cp.async.commit_group;" ::: "memory");
}

__device__ __forceinline__ void mainloop128(uint32_t smem, int tid,
                                            const __half* const srcs[4],
                                            float C[4][4][4]) {
    const int l = tid & 31, wid = tid >> 5;
    const int wm = wid >> 2, wn = wid & 3;

    const int a_row = l & 15;
    const int a_cb  = (l >> 4) << 4;
    const int b_row = (((l >> 4) & 1) << 3) + (l & 7);
    const int b_cb  = ((l >> 3) & 1) << 4;

    load128(smem, tid, srcs, 0);

#pragma unroll 1
    for (int ch = 0; ch < 8; ch++) {
        uint32_t cur = smem + (ch & 1) * BUF128;
        if (ch < 7) {
            load128(smem + ((ch + 1) & 1) * BUF128, tid, srcs, (ch + 1) * 64);
            asm volatile("cp.async.wait_group 1;" ::: "memory");
        } else {
            asm volatile("cp.async.wait_group 0;" ::: "memory");
        }
        __syncthreads();

#pragma unroll
        for (int ks = 0; ks < 4; ks++) {
            uint32_t B[2][4][2];
#pragma unroll
            for (int s = 0; s < 2; s++) {
#pragma unroll
                for (int nh = 0; nh < 2; nh++) {
                    uint32_t ad = cur + ((2 + s) << 14) +
                        SWZ((wn * 32 + nh * 16 + b_row) * 128 + ks * 32 + b_cb);
                    uint32_t r0, r1, r2, r3;
                    ldsm4(r0, r1, r2, r3, ad);
                    B[s][nh * 2][0] = r0; B[s][nh * 2][1] = r1;
                    B[s][nh * 2 + 1][0] = r2; B[s][nh * 2 + 1][1] = r3;
                }
            }
#pragma unroll
            for (int sa = 0; sa < 2; sa++) {
                uint32_t A[4][4];
#pragma unroll
                for (int mf = 0; mf < 4; mf++) {
                    uint32_t ad = cur + (sa << 14) +
                        SWZ((wm * 64 + mf * 16 + a_row) * 128 + ks * 32 + a_cb);
                    ldsm4(A[mf][0], A[mf][1], A[mf][2], A[mf][3], ad);
                }
#pragma unroll
                for (int sb = 0; sb < 2 - sa; sb++) {
#pragma unroll
                    for (int mf = 0; mf < 4; mf++)
#pragma unroll
                        for (int nf = 0; nf < 4; nf++)
                            mma_f16(C[mf][nf], A[mf], B[sb][nf]);
                }
            }
        }
        __syncthreads();
    }
}

// ---------------------------------------------------------------------------
// prep_E: E = emb @ W_ih^T + bias  (M=512, N=2048, K=512), grid (16, 4)
// ---------------------------------------------------------------------------
__global__ __launch_bounds__(256, 1) void prep_E_kernel() {
    extern __shared__ char dsm[];
    uint32_t smem = (smem_u32(dsm) + 1023) & ~1023u;
    int tid = threadIdx.x;
    int l = tid & 31, wid = tid >> 5;
    int wm = wid >> 2, wn = wid & 3, tg = l & 3;
    int n0 = blockIdx.x * 128, m0 = blockIdx.y * 128;

    const __half* srcs[4] = {
        g_emb[0] + (size_t)m0 * 512, g_emb[1] + (size_t)m0 * 512,
        g_Wih[0] + (size_t)n0 * 512, g_Wih[1] + (size_t)n0 * 512};

    float C[4][4][4] = {};
    mainloop128(smem, tid, srcs, C);

#pragma unroll
    for (int mf = 0; mf < 4; mf++)
#pragma unroll
        for (int nf = 0; nf < 4; nf++) {
            int n = n0 + wn * 32 + nf * 8 + tg * 2;
#pragma unroll
            for (int rh = 0; rh < 2; rh++) {
                int m = m0 + wm * 64 + mf * 16 + (l >> 2) + rh * 8;
                float2 v = make_float2(
                    C[mf][nf][rh * 2 + 0] * INV512 + g_bias[n],
                    C[mf][nf][rh * 2 + 1] * INV512 + g_bias[n + 1]);
                *(float2*)&g_E[(size_t)m * G4H + n] = v;
            }
        }
}

// ---------------------------------------------------------------------------
// Gates: gates = h @ W_hh^T (+ E[token]) -> fused LSTM cell.
// Tile 128x128, grid (16, 8).  Token from g_amax[rd^1], prefetched after the
// PDL dependency sync; clears g_amax[rd] for this step's logits.
// ---------------------------------------------------------------------------
__global__ __launch_bounds__(256, 1) void gates_tc(int rd) {
    extern __shared__ char dsm[];
    uint32_t smem = (smem_u32(dsm) + 1023) & ~1023u;
    int tid = threadIdx.x;
    int l = tid & 31, wid = tid >> 5;
    int wm = wid >> 2, wn = wid & 3, tg = l & 3;
    int n0 = blockIdx.x * 128, m0 = blockIdx.y * 128;
    int wr = rd ^ 1;

    // PDL: wait for the previous logits grid before reading g_amax / g_hs.
    cudaGridDependencySynchronize();

    // Prefetch previous-step argmax keys (hides amax->E LDG chain behind GEMM)
    int tok8[4][2];
#pragma unroll
    for (int mf = 0; mf < 4; mf++)
#pragma unroll
        for (int rh = 0; rh < 2; rh++) {
            int m = m0 + wm * 64 + mf * 16 + (l >> 2) + rh * 8;
            tok8[mf][rh] = 511 - (int)(g_amax[wr][m] & 0x3ffull);
        }

    if (tid < 128) g_amax[rd][m0 + tid] = 0ull;   // clear for this step's logits

    const __half* srcs[4] = {
        g_hs[rd][0] + (size_t)m0 * 512, g_hs[rd][1] + (size_t)m0 * 512,
        g_Whh[0] + (size_t)n0 * 512, g_Whh[1] + (size_t)n0 * 512};

    float C[4][4][4] = {};
    mainloop128(smem, tid, srcs, C);

    // Let the dependent logits kernel begin its prologue while we run the
    // epilogue (it still gridDepSync's on our full completion).
    cudaTriggerProgrammaticLaunchCompletion();

    // Epilogue: even-tg lane holds (i,f) pre-acts; partner (tg^1) holds (g,o).
#pragma unroll
    for (int mf = 0; mf < 4; mf++)
#pragma unroll
        for (int rh = 0; rh < 2; rh++) {
            int m = m0 + wm * 64 + mf * 16 + (l >> 2) + rh * 8;
            const float* Erow = g_E + (size_t)tok8[mf][rh] * G4H;
#pragma unroll
            for (int nf = 0; nf < 4; nf++) {
                float own0 = C[mf][nf][rh * 2 + 0];
                float own1 = C[mf][nf][rh * 2 + 1];
                float p0 = __shfl_xor_sync(0xffffffffu, own0, 1);
                float p1 = __shfl_xor_sync(0xffffffffu, own1, 1);
                if (!(tg & 1)) {
                    int n = n0 + wn * 32 + nf * 8 + tg * 2;   // = 4*j
                    int j = n >> 2;
                    float4 e = *(const float4*)&Erow[n];
                    float gi = own0 * INV512 + e.x;
                    float gf = own1 * INV512 + e.y;
                    float gg = p0 * INV512 + e.z;
                    float go = p1 * INV512 + e.w;
                    float is = 1.f / (1.f + expf(-gi));
                    float fs = 1.f / (1.f + expf(-gf));
                    float os = 1.f / (1.f + expf(-go));
                    size_t hx = (size_t)m * HID + j;
                    float cn = fs * g_c[hx] + is * tanhf(gg);
                    g_c[hx] = cn;
                    float hn = os * tanhf(cn);
                    split2(16.0f * hn, g_hs[wr][0][hx], g_hs[wr][1][hx]);
                }
            }
        }
}

// ---------------------------------------------------------------------------
// Logits: out = h @ W_out^T + b_out, fused per-row argmax via atomicMax.
// Tile 64x64, grid (8, 16), 256 threads, warp tile 32x16 (2Mx4N).
// ---------------------------------------------------------------------------
#define TILE64   8192
#define BUF64    (4 * TILE64)          // 32768
#define SMEM64   (2 * BUF64 + 1024)

__device__ __forceinline__ void load64(uint32_t bufb, int tid,
                                       const __half* const srcs[4], int koff) {
#pragma unroll
    for (int i = 0; i < 8; i++) {
        int t = i >> 1;
        int u = tid + (i & 1) * 256;
        int row = u >> 3;
        int cb = u & 7;
        cp16(bufb + (t << 13) + SWZ(row * 128 + cb * 16),
             srcs[t] + (size_t)row * 512 + koff + cb * 8);
    }
    asm volatile("cp.async.commit_group;" ::: "memory");
}

__global__ __launch_bounds__(256, 1) void logits_tc(int ph, int ab,
                                                    const float* __restrict__ bo,
                                                    float* __restrict__ out_t) {
    extern __shared__ char dsm[];
    uint32_t smem = (smem_u32(dsm) + 1023) & ~1023u;
    int tid = threadIdx.x;
    int l = tid & 31, wid = tid >> 5;
    int wm = wid >> 2, wn = wid & 3, tg = l & 3;
    int n0 = blockIdx.x * 64, m0 = blockIdx.y * 64;

    // PDL: wait for gates to finish writing g_hs[ph] / g_amax[ab] clear.
    cudaGridDependencySynchronize();

    const __half* srcs[4] = {
        g_hs[ph][0] + (size_t)m0 * 512, g_hs[ph][1] + (size_t)m0 * 512,
        g_Wo[0] + (size_t)n0 * 512, g_Wo[1] + (size_t)n0 * 512};

    const int a_row = l & 15;
    const int a_cb  = (l >> 4) << 4;
    const int b_row = (((l >> 4) & 1) << 3) + (l & 7);
    const int b_cb  = ((l >> 3) & 1) << 4;

    float C[2][2][4] = {};

    load64(smem, tid, srcs, 0);
#pragma unroll 1
    for (int ch = 0; ch < 8; ch++) {
        uint32_t cur = smem + (ch & 1) * BUF64;
        if (ch < 7) {
            load64(smem + ((ch + 1) & 1) * BUF64, tid, srcs, (ch + 1) * 64);
            asm volatile("cp.async.wait_group 1;" ::: "memory");
        } else {
            asm volatile("cp.async.wait_group 0;" ::: "memory");
        }
        __syncthreads();

#pragma unroll
        for (int ks = 0; ks < 4; ks++) {
            uint32_t B[2][2][2];
#pragma unroll
            for (int s = 0; s < 2; s++) {
                uint32_t ad = cur + ((2 + s) << 13) +
                    SWZ((wn * 16 + b_row) * 128 + ks * 32 + b_cb);
                uint32_t r0, r1, r2, r3;
                ldsm4(r0, r1, r2, r3, ad);
                B[s][0][0] = r0; B[s][0][1] = r1;
                B[s][1][0] = r2; B[s][1][1] = r3;
            }
#pragma unroll
            for (int sa = 0; sa < 2; sa++) {
                uint32_t A[2][4];
#pragma unroll
                for (int mf = 0; mf < 2; mf++) {
                    uint32_t ad = cur + (sa << 13) +
                        SWZ((wm * 32 + mf * 16 + a_row) * 128 + ks * 32 + a_cb);
                    ldsm4(A[mf][0], A[mf][1], A[mf][2], A[mf][3], ad);
                }
#pragma unroll
                for (int sb = 0; sb < 2 - sa; sb++) {
#pragma unroll
                    for (int mf = 0; mf < 2; mf++)
#pragma unroll
                        for (int nf = 0; nf < 2; nf++)
                            mma_f16(C[mf][nf], A[mf], B[sb][nf]);
                }
            }
        }
        __syncthreads();
    }

    // Next gates may start its prologue while we run the epilogue.
    cudaTriggerProgrammaticLaunchCompletion();

#pragma unroll
    for (int mf = 0; mf < 2; mf++)
#pragma unroll
        for (int rh = 0; rh < 2; rh++) {
            int m = m0 + wm * 32 + mf * 16 + (l >> 2) + rh * 8;
            u64 best = 0ull;
#pragma unroll
            for (int nf = 0; nf < 2; nf++) {
                int n = n0 + wn * 16 + nf * 8 + tg * 2;
                float v0 = C[mf][nf][rh * 2 + 0] * INV512 + bo[n];
                float v1 = C[mf][nf][rh * 2 + 1] * INV512 + bo[n + 1];
                *(float2*)&out_t[(size_t)m * VOCAB + n] = make_float2(v0, v1);
                u64 k0 = amax_key(v0, n), k1 = amax_key(v1, n + 1);
                if (k0 > best) best = k0;
                if (k1 > best) best = k1;
            }
            u64 o1 = __shfl_xor_sync(0xffffffffu, best, 1);
            if (o1 > best) best = o1;
            u64 o2 = __shfl_xor_sync(0xffffffffu, best, 2);
            if (o2 > best) best = o2;
            if (tg == 0) atomicMax(&g_amax[ab][m], best);
        }
}

// ---------------------------------------------------------------------------
// Launch (step kernels use Programmatic Dependent Launch)
// ---------------------------------------------------------------------------
extern "C" void kernel_launch(void* const* d_in, const int* in_sizes, int n_in,
                              void* d_out, int out_size) {
    const float* enc_h = (const float*)d_in[2];
    const float* enc_c = (const float*)d_in[3];
    const float* emb   = (const float*)d_in[4];
    const float* W_ih  = (const float*)d_in[5];
    const float* W_hh  = (const float*)d_in[6];
    const float* b_ih  = (const float*)d_in[7];
    const float* b_hh  = (const float*)d_in[8];
    const float* W_out = (const float*)d_in[9];
    const float* b_out = (const float*)d_in[10];
    float* out = (float*)d_out;

    cudaFuncSetAttribute(prep_E_kernel, cudaFuncAttributeMaxDynamicSharedMemorySize, SMEM128);
    cudaFuncSetAttribute(gates_tc, cudaFuncAttributeMaxDynamicSharedMemorySize, SMEM128);
    cudaFuncSetAttribute(logits_tc, cudaFuncAttributeMaxDynamicSharedMemorySize, SMEM64);

    prep_gates<<<(G4H * HID) / 256, 256>>>(W_ih, W_hh, b_ih, b_hh);
    prep_out<<<(VOCAB * HID) / 256, 256>>>(W_out, emb);
    init_state_tc<<<(BATCH * HID) / 256, 256>>>(enc_h, enc_c);
    prep_E_kernel<<<dim3(16, 4), 256, SMEM128>>>();

    cudaLaunchAttribute pdl[1];
    pdl[0].id = cudaLaunchAttributeProgrammaticStreamSerialization;
    pdl[0].val.programmaticStreamSerializationAllowed = 1;

    for (int t = 0; t < T_STEPS; t++) {
        int rd = t & 1;
        int ab = rd;
        int ph = rd ^ 1;

        cudaLaunchConfig_t cfgG = {};
        cfgG.gridDim = dim3(16, 8);
        cfgG.blockDim = dim3(256);
        cfgG.dynamicSmemBytes = SMEM128;
        cfgG.attrs = pdl;
        cfgG.numAttrs = 1;
        cudaLaunchKernelEx(&cfgG, gates_tc, rd);

        float* logits_t = out + (size_t)t * BATCH * VOCAB;
        cudaLaunchConfig_t cfgL = {};
        cfgL.gridDim = dim3(8, 16);
        cfgL.blockDim = dim3(256);
        cfgL.dynamicSmemBytes = SMEM64;
        cfgL.attrs = pdl;
        cfgL.numAttrs = 1;
        cudaLaunchKernelEx(&cfgL, logits_tc, ph, ab, b_out, logits_t);
    }
}

// round 15
// speedup vs baseline: 1.1283x; 1.1283x over previous
#include <cuda_runtime.h>
#include <cuda_fp16.h>
#include <math.h>
#include <stdint.h>

#define T_STEPS 64
#define BATCH   1024
#define HID     512
#define VOCAB   512
#define G4H     2048
#define NCTA    128

typedef unsigned long long u64;

// ---------------------------------------------------------------------------
// Device-global scratch (allocation-free)
// A-side operands (h, emb) pre-scaled by 16; B-side weights by 32.
// GEMM accumulators therefore carry 512x; epilogues multiply by 1/512.
// ---------------------------------------------------------------------------
__device__ float  g_c[BATCH * HID];            // cell state fp32
__device__ __half g_hs[2][2][BATCH * HID];     // 16*h 2-way fp16 splits, ping-pong
__device__ __half g_Wih[2][G4H * HID];         // 32*W_ih splits (gate-interleaved)
__device__ __half g_Whh[2][G4H * HID];         // 32*W_hh splits (gate-interleaved)
__device__ __half g_Wo[2][VOCAB * HID];        // 32*W_out splits
__device__ __half g_emb[2][VOCAB * HID];       // 16*embedding splits
__device__ float  g_bias[G4H];                 // gate-interleaved b_ih+b_hh
__device__ float  g_E[VOCAB * G4H];            // emb @ W_ih^T + bias (fp32, true scale)
__device__ u64    g_amax[2][BATCH];            // packed (mapped logit, 511-col)
__device__ unsigned g_barCount;                // grid barrier arrivals
__device__ unsigned g_barGen;                  // grid barrier generation

#define INV512 (1.0f / 512.0f)

// ---------------------------------------------------------------------------
// Helpers
// ---------------------------------------------------------------------------
__device__ __forceinline__ uint32_t smem_u32(const void* p) {
    uint32_t a;
    asm("{ .reg .u64 t; cvta.to.shared.u64 t, %1; cvt.u32.u64 %0, t; }"
        : "=r"(a) : "l"(p));
    return a;
}

#define SWZ(x) ((x) ^ (((x) >> 3) & 0x70))

__device__ __forceinline__ void cp16(uint32_t dst, const void* src) {
    asm volatile("cp.async.cg.shared.global [%0], [%1], 16;" :: "r"(dst), "l"(src));
}

__device__ __forceinline__ void ldsm4(uint32_t& r0, uint32_t& r1,
                                      uint32_t& r2, uint32_t& r3, uint32_t addr) {
    asm volatile("ldmatrix.sync.aligned.m8n8.x4.shared.b16 {%0,%1,%2,%3}, [%4];"
                 : "=r"(r0), "=r"(r1), "=r"(r2), "=r"(r3) : "r"(addr));
}

__device__ __forceinline__ void mma_f16(float c[4], const uint32_t a[4],
                                        const uint32_t b[2]) {
    asm volatile(
        "mma.sync.aligned.m16n8k16.row.col.f32.f16.f16.f32 "
        "{%0,%1,%2,%3}, {%4,%5,%6,%7}, {%8,%9}, {%0,%1,%2,%3};"
        : "+f"(c[0]), "+f"(c[1]), "+f"(c[2]), "+f"(c[3])
        : "r"(a[0]), "r"(a[1]), "r"(a[2]), "r"(a[3]), "r"(b[0]), "r"(b[1]));
}

// Exact 2-way fp16 split of a pre-scaled value
__device__ __forceinline__ void split2(float v, __half& s0, __half& s1) {
    s0 = __float2half_rn(v);
    s1 = __float2half_rn(v - __half2float(s0));
}

// Monotone float->u32 map; key packs (value, 511-col) for first-max argmax
__device__ __forceinline__ u64 amax_key(float v, int col) {
    uint32_t u = __float_as_uint(v);
    uint32_t mu = (u & 0x80000000u) ? ~u : (u | 0x80000000u);
    return ((u64)mu << 32) | (uint32_t)(511 - col);
}

// Grid-wide barrier (all NCTA CTAs co-resident at occ 1 => no deadlock).
__device__ __forceinline__ void grid_sync() {
    __syncthreads();
    if (threadIdx.x == 0) {
        __threadfence();
        unsigned gen = atomicAdd(&g_barGen, 0u);
        unsigned t = atomicAdd(&g_barCount, 1u);
        if (t == NCTA - 1) {
            atomicExch(&g_barCount, 0u);
            __threadfence();
            atomicAdd(&g_barGen, 1u);
        } else {
            while (atomicAdd(&g_barGen, 0u) == gen) {}
        }
        __threadfence();
    }
    __syncthreads();
}

// ---------------------------------------------------------------------------
// Prep kernels
// ---------------------------------------------------------------------------
__global__ void prep_gates(const float* __restrict__ Wih, const float* __restrict__ Whh,
                           const float* __restrict__ bih, const float* __restrict__ bhh) {
    int idx = blockIdx.x * blockDim.x + threadIdx.x;    // [0, G4H*HID)
    int n = idx >> 9;
    int k = idx & 511;
    int orig = ((n & 3) << 9) + (n >> 2);               // interleave i,f,g,o per j
    split2(32.0f * Wih[(size_t)orig * 512 + k], g_Wih[0][idx], g_Wih[1][idx]);
    split2(32.0f * Whh[(size_t)orig * 512 + k], g_Whh[0][idx], g_Whh[1][idx]);
    if (k == 0) g_bias[n] = bih[orig] + bhh[orig];
}

__global__ void prep_out(const float* __restrict__ Wout, const float* __restrict__ emb) {
    int idx = blockIdx.x * blockDim.x + threadIdx.x;    // [0, VOCAB*HID)
    split2(32.0f * Wout[idx], g_Wo[0][idx], g_Wo[1][idx]);
    split2(16.0f * emb[idx], g_emb[0][idx], g_emb[1][idx]);
}

__global__ void init_state_tc(const float* __restrict__ ench,
                              const float* __restrict__ encc) {
    int idx = blockIdx.x * blockDim.x + threadIdx.x;    // [0, BATCH*HID)
    g_c[idx] = encc[idx];
    split2(16.0f * ench[idx], g_hs[0][0][idx], g_hs[0][1][idx]);
    if ((idx & 511) == 0) g_amax[1][idx >> 9] = 511ull;  // decodes to SOS token 0
    if (idx == 0) g_barCount = 0;                        // barrier state reset
}

// ---------------------------------------------------------------------------
// 128x128 main loop (K=512 in 8 chunks of 64), 256 threads, 8 warps (2Mx4N)
// Warp tile 64x32.  smem: double buffer of 4 tiles x 16KB (2 A splits, 2 B).
// Split products (0,0),(0,1),(1,0); one A-split live at a time.
// (Round-12-proven configuration.)
// ---------------------------------------------------------------------------
#define TILE128   16384
#define BUF128    (4 * TILE128)        // 65536
#define SMEM128   (2 * BUF128 + 1024)

__device__ __forceinline__ void load128(uint32_t bufb, int tid,
                                        const __half* const srcs[4], int koff) {
#pragma unroll
    for (int i = 0; i < 16; i++) {
        int t = i >> 2;
        int u = tid + (i & 3) * 256;
        int row = u >> 3;
        int cb = u & 7;
        cp16(bufb + (t << 14) + SWZ(row * 128 + cb * 16),
             srcs[t] + (size_t)row * 512 + koff + cb * 8);
    }
    asm volatile("cp.async.commit_group;" ::: "memory");
}

__device__ __forceinline__ void mainloop128(uint32_t smem, int tid,
                                            const __half* const srcs[4],
                                            float C[4][4][4]) {
    const int l = tid & 31, wid = tid >> 5;
    const int wm = wid >> 2, wn = wid & 3;

    const int a_row = l & 15;
    const int a_cb  = (l >> 4) << 4;
    const int b_row = (((l >> 4) & 1) << 3) + (l & 7);
    const int b_cb  = ((l >> 3) & 1) << 4;

    load128(smem, tid, srcs, 0);

#pragma unroll 1
    for (int ch = 0; ch < 8; ch++) {
        uint32_t cur = smem + (ch & 1) * BUF128;
        if (ch < 7) {
            load128(smem + ((ch + 1) & 1) * BUF128, tid, srcs, (ch + 1) * 64);
            asm volatile("cp.async.wait_group 1;" ::: "memory");
        } else {
            asm volatile("cp.async.wait_group 0;" ::: "memory");
        }
        __syncthreads();

#pragma unroll
        for (int ks = 0; ks < 4; ks++) {
            uint32_t B[2][4][2];
#pragma unroll
            for (int s = 0; s < 2; s++) {
#pragma unroll
                for (int nh = 0; nh < 2; nh++) {
                    uint32_t ad = cur + ((2 + s) << 14) +
                        SWZ((wn * 32 + nh * 16 + b_row) * 128 + ks * 32 + b_cb);
                    uint32_t r0, r1, r2, r3;
                    ldsm4(r0, r1, r2, r3, ad);
                    B[s][nh * 2][0] = r0; B[s][nh * 2][1] = r1;
                    B[s][nh * 2 + 1][0] = r2; B[s][nh * 2 + 1][1] = r3;
                }
            }
#pragma unroll
            for (int sa = 0; sa < 2; sa++) {
                uint32_t A[4][4];
#pragma unroll
                for (int mf = 0; mf < 4; mf++) {
                    uint32_t ad = cur + (sa << 14) +
                        SWZ((wm * 64 + mf * 16 + a_row) * 128 + ks * 32 + a_cb);
                    ldsm4(A[mf][0], A[mf][1], A[mf][2], A[mf][3], ad);
                }
#pragma unroll
                for (int sb = 0; sb < 2 - sa; sb++) {
#pragma unroll
                    for (int mf = 0; mf < 4; mf++)
#pragma unroll
                        for (int nf = 0; nf < 4; nf++)
                            mma_f16(C[mf][nf], A[mf], B[sb][nf]);
                }
            }
        }
        __syncthreads();
    }
}

// ---------------------------------------------------------------------------
// prep_E: E = emb @ W_ih^T + bias  (M=512, N=2048, K=512), grid (16, 4)
// ---------------------------------------------------------------------------
__global__ __launch_bounds__(256, 1) void prep_E_kernel() {
    extern __shared__ char dsm[];
    uint32_t smem = (smem_u32(dsm) + 1023) & ~1023u;
    int tid = threadIdx.x;
    int l = tid & 31, wid = tid >> 5;
    int wm = wid >> 2, wn = wid & 3, tg = l & 3;
    int n0 = blockIdx.x * 128, m0 = blockIdx.y * 128;

    const __half* srcs[4] = {
        g_emb[0] + (size_t)m0 * 512, g_emb[1] + (size_t)m0 * 512,
        g_Wih[0] + (size_t)n0 * 512, g_Wih[1] + (size_t)n0 * 512};

    float C[4][4][4] = {};
    mainloop128(smem, tid, srcs, C);

#pragma unroll
    for (int mf = 0; mf < 4; mf++)
#pragma unroll
        for (int nf = 0; nf < 4; nf++) {
            int n = n0 + wn * 32 + nf * 8 + tg * 2;
#pragma unroll
            for (int rh = 0; rh < 2; rh++) {
                int m = m0 + wm * 64 + mf * 16 + (l >> 2) + rh * 8;
                float2 v = make_float2(
                    C[mf][nf][rh * 2 + 0] * INV512 + g_bias[n],
                    C[mf][nf][rh * 2 + 1] * INV512 + g_bias[n + 1]);
                *(float2*)&g_E[(size_t)m * G4H + n] = v;
            }
        }
}

// ---------------------------------------------------------------------------
// Logits tile helpers (64x64 tile inside the persistent kernel)
// ---------------------------------------------------------------------------
#define TILE64   8192
#define BUF64    (4 * TILE64)          // 32768

__device__ __forceinline__ void load64(uint32_t bufb, int tid,
                                       const __half* const srcs[4], int koff) {
#pragma unroll
    for (int i = 0; i < 8; i++) {
        int t = i >> 1;
        int u = tid + (i & 1) * 256;
        int row = u >> 3;
        int cb = u & 7;
        cp16(bufb + (t << 13) + SWZ(row * 128 + cb * 16),
             srcs[t] + (size_t)row * 512 + koff + cb * 8);
    }
    asm volatile("cp.async.commit_group;" ::: "memory");
}

// ---------------------------------------------------------------------------
// Persistent step kernel: 64 x (gates -> barrier -> logits -> barrier)
// grid = 128 CTAs x 256 threads, occ 1 each => all co-resident (wave 1).
// ---------------------------------------------------------------------------
__global__ __launch_bounds__(256, 1) void step_persistent(
    const float* __restrict__ bo, float* __restrict__ out) {
    extern __shared__ char dsm[];
    uint32_t smem = (smem_u32(dsm) + 1023) & ~1023u;
    int tid = threadIdx.x;
    int bid = blockIdx.x;
    int l = tid & 31, wid = tid >> 5;
    int wm = wid >> 2, wn = wid & 3, tg = l & 3;

    // gates tile (128x128): 16 n-tiles x 8 m-tiles
    const int gn0 = (bid & 15) * 128;
    const int gm0 = (bid >> 4) * 128;
    // logits tile (64x64): 8 n-tiles x 16 m-tiles
    const int ln0 = (bid & 7) * 64;
    const int lm0 = (bid >> 3) * 64;

    const int a_row = l & 15;
    const int a_cb  = (l >> 4) << 4;
    const int b_row = (((l >> 4) & 1) << 3) + (l & 7);
    const int b_cb  = ((l >> 3) & 1) << 4;

#pragma unroll 1
    for (int t = 0; t < T_STEPS; t++) {
        int rd = t & 1;
        int wr = rd ^ 1;

        // ---------------- gates phase ----------------
        // Prefetch previous-step argmax tokens (prev logits + barrier ordered)
        int tok8[4][2];
#pragma unroll
        for (int mf = 0; mf < 4; mf++)
#pragma unroll
            for (int rh = 0; rh < 2; rh++) {
                int m = gm0 + wm * 64 + mf * 16 + (l >> 2) + rh * 8;
                tok8[mf][rh] = 511 - (int)(g_amax[wr][m] & 0x3ffull);
            }

        if (tid < 128) g_amax[rd][gm0 + tid] = 0ull;  // clear for this step

        {
            const __half* srcs[4] = {
                g_hs[rd][0] + (size_t)gm0 * 512, g_hs[rd][1] + (size_t)gm0 * 512,
                g_Whh[0] + (size_t)gn0 * 512, g_Whh[1] + (size_t)gn0 * 512};

            float C[4][4][4] = {};
            mainloop128(smem, tid, srcs, C);

            // Epilogue: even-tg lane holds (i,f); partner (tg^1) holds (g,o).
#pragma unroll
            for (int mf = 0; mf < 4; mf++)
#pragma unroll
                for (int rh = 0; rh < 2; rh++) {
                    int m = gm0 + wm * 64 + mf * 16 + (l >> 2) + rh * 8;
                    const float* Erow = g_E + (size_t)tok8[mf][rh] * G4H;
#pragma unroll
                    for (int nf = 0; nf < 4; nf++) {
                        float own0 = C[mf][nf][rh * 2 + 0];
                        float own1 = C[mf][nf][rh * 2 + 1];
                        float p0 = __shfl_xor_sync(0xffffffffu, own0, 1);
                        float p1 = __shfl_xor_sync(0xffffffffu, own1, 1);
                        if (!(tg & 1)) {
                            int n = gn0 + wn * 32 + nf * 8 + tg * 2;  // = 4*j
                            int j = n >> 2;
                            float4 e = *(const float4*)&Erow[n];
                            float gi = own0 * INV512 + e.x;
                            float gf = own1 * INV512 + e.y;
                            float gg = p0 * INV512 + e.z;
                            float go = p1 * INV512 + e.w;
                            float is = 1.f / (1.f + expf(-gi));
                            float fs = 1.f / (1.f + expf(-gf));
                            float os = 1.f / (1.f + expf(-go));
                            size_t hx = (size_t)m * HID + j;
                            float cn = fs * g_c[hx] + is * tanhf(gg);
                            g_c[hx] = cn;
                            float hn = os * tanhf(cn);
                            split2(16.0f * hn, g_hs[wr][0][hx], g_hs[wr][1][hx]);
                        }
                    }
                }
        }

        grid_sync();   // h splits + amax clear visible chip-wide

        // ---------------- logits phase ----------------
        {
            float* out_t = out + (size_t)t * BATCH * VOCAB;
            const __half* srcs[4] = {
                g_hs[wr][0] + (size_t)lm0 * 512, g_hs[wr][1] + (size_t)lm0 * 512,
                g_Wo[0] + (size_t)ln0 * 512, g_Wo[1] + (size_t)ln0 * 512};

            float C[2][2][4] = {};

            load64(smem, tid, srcs, 0);
#pragma unroll 1
            for (int ch = 0; ch < 8; ch++) {
                uint32_t cur = smem + (ch & 1) * BUF64;
                if (ch < 7) {
                    load64(smem + ((ch + 1) & 1) * BUF64, tid, srcs, (ch + 1) * 64);
                    asm volatile("cp.async.wait_group 1;" ::: "memory");
                } else {
                    asm volatile("cp.async.wait_group 0;" ::: "memory");
                }
                __syncthreads();

#pragma unroll
                for (int ks = 0; ks < 4; ks++) {
                    uint32_t B[2][2][2];
#pragma unroll
                    for (int s = 0; s < 2; s++) {
                        uint32_t ad = cur + ((2 + s) << 13) +
                            SWZ((wn * 16 + b_row) * 128 + ks * 32 + b_cb);
                        uint32_t r0, r1, r2, r3;
                        ldsm4(r0, r1, r2, r3, ad);
                        B[s][0][0] = r0; B[s][0][1] = r1;
                        B[s][1][0] = r2; B[s][1][1] = r3;
                    }
#pragma unroll
                    for (int sa = 0; sa < 2; sa++) {
                        uint32_t A[2][4];
#pragma unroll
                        for (int mf = 0; mf < 2; mf++) {
                            uint32_t ad = cur + (sa << 13) +
                                SWZ((wm * 32 + mf * 16 + a_row) * 128 + ks * 32 + a_cb);
                            ldsm4(A[mf][0], A[mf][1], A[mf][2], A[mf][3], ad);
                        }
#pragma unroll
                        for (int sb = 0; sb < 2 - sa; sb++) {
#pragma unroll
                            for (int mf = 0; mf < 2; mf++)
#pragma unroll
                                for (int nf = 0; nf < 2; nf++)
                                    mma_f16(C[mf][nf], A[mf], B[sb][nf]);
                        }
                    }
                }
                __syncthreads();
            }

#pragma unroll
            for (int mf = 0; mf < 2; mf++)
#pragma unroll
                for (int rh = 0; rh < 2; rh++) {
                    int m = lm0 + wm * 32 + mf * 16 + (l >> 2) + rh * 8;
                    u64 best = 0ull;
#pragma unroll
                    for (int nf = 0; nf < 2; nf++) {
                        int n = ln0 + wn * 16 + nf * 8 + tg * 2;
                        float v0 = C[mf][nf][rh * 2 + 0] * INV512 + bo[n];
                        float v1 = C[mf][nf][rh * 2 + 1] * INV512 + bo[n + 1];
                        *(float2*)&out_t[(size_t)m * VOCAB + n] = make_float2(v0, v1);
                        u64 k0 = amax_key(v0, n), k1 = amax_key(v1, n + 1);
                        if (k0 > best) best = k0;
                        if (k1 > best) best = k1;
                    }
                    u64 o1 = __shfl_xor_sync(0xffffffffu, best, 1);
                    if (o1 > best) best = o1;
                    u64 o2 = __shfl_xor_sync(0xffffffffu, best, 2);
                    if (o2 > best) best = o2;
                    if (tg == 0) atomicMax(&g_amax[rd][m], best);
                }
        }

        grid_sync();   // argmax keys visible before next gates phase
    }
}

// ---------------------------------------------------------------------------
// Launch
// ---------------------------------------------------------------------------
extern "C" void kernel_launch(void* const* d_in, const int* in_sizes, int n_in,
                              void* d_out, int out_size) {
    const float* enc_h = (const float*)d_in[2];
    const float* enc_c = (const float*)d_in[3];
    const float* emb   = (const float*)d_in[4];
    const float* W_ih  = (const float*)d_in[5];
    const float* W_hh  = (const float*)d_in[6];
    const float* b_ih  = (const float*)d_in[7];
    const float* b_hh  = (const float*)d_in[8];
    const float* W_out = (const float*)d_in[9];
    const float* b_out = (const float*)d_in[10];
    float* out = (float*)d_out;

    cudaFuncSetAttribute(prep_E_kernel, cudaFuncAttributeMaxDynamicSharedMemorySize, SMEM128);
    cudaFuncSetAttribute(step_persistent, cudaFuncAttributeMaxDynamicSharedMemorySize, SMEM128);

    prep_gates<<<(G4H * HID) / 256, 256>>>(W_ih, W_hh, b_ih, b_hh);
    prep_out<<<(VOCAB * HID) / 256, 256>>>(W_out, emb);
    init_state_tc<<<(BATCH * HID) / 256, 256>>>(enc_h, enc_c);
    prep_E_kernel<<<dim3(16, 4), 256, SMEM128>>>();

    step_persistent<<<NCTA, 256, SMEM128>>>(b_out, out);
}

// round 16
// speedup vs baseline: 1.2045x; 1.0675x over previous
#include <cuda_runtime.h>
#include <cuda_fp16.h>
#include <math.h>
#include <stdint.h>

#define T_STEPS 64
#define BATCH   1024
#define HID     512
#define VOCAB   512
#define G4H     2048
#define NCTA    128

typedef unsigned long long u64;

// ---------------------------------------------------------------------------
// Device-global scratch (allocation-free)
// A-side operands (h, emb) pre-scaled by 16; B-side weights by 32.
// GEMM accumulators therefore carry 512x; epilogues multiply by 1/512.
// ---------------------------------------------------------------------------
__device__ float  g_c[BATCH * HID];            // cell state fp32
__device__ __half g_hs[2][2][BATCH * HID];     // 16*h 2-way fp16 splits, ping-pong
__device__ __half g_Wih[2][G4H * HID];         // 32*W_ih splits (gate-interleaved)
__device__ __half g_Whh[2][G4H * HID];         // 32*W_hh splits (gate-interleaved)
__device__ __half g_Wo[2][VOCAB * HID];        // 32*W_out splits
__device__ __half g_emb[2][VOCAB * HID];       // 16*embedding splits
__device__ float  g_bias[G4H];                 // gate-interleaved b_ih+b_hh
__device__ float  g_E[VOCAB * G4H];            // emb @ W_ih^T + bias (fp32, true scale)
__device__ u64    g_amax[2][BATCH];            // packed (mapped logit, 511-col)
__device__ unsigned g_hcnt[T_STEPS][8];        // per-(step, m-block) h-ready count
__device__ unsigned g_acnt[T_STEPS][8];        // per-(step, m-block) amax-ready count

#define INV512 (1.0f / 512.0f)

// ---------------------------------------------------------------------------
// Helpers
// ---------------------------------------------------------------------------
__device__ __forceinline__ uint32_t smem_u32(const void* p) {
    uint32_t a;
    asm("{ .reg .u64 t; cvta.to.shared.u64 t, %1; cvt.u32.u64 %0, t; }"
        : "=r"(a) : "l"(p));
    return a;
}

#define SWZ(x) ((x) ^ (((x) >> 3) & 0x70))

__device__ __forceinline__ void cp16(uint32_t dst, const void* src) {
    asm volatile("cp.async.cg.shared.global [%0], [%1], 16;" :: "r"(dst), "l"(src));
}

__device__ __forceinline__ void ldsm4(uint32_t& r0, uint32_t& r1,
                                      uint32_t& r2, uint32_t& r3, uint32_t addr) {
    asm volatile("ldmatrix.sync.aligned.m8n8.x4.shared.b16 {%0,%1,%2,%3}, [%4];"
                 : "=r"(r0), "=r"(r1), "=r"(r2), "=r"(r3) : "r"(addr));
}

__device__ __forceinline__ void mma_f16(float c[4], const uint32_t a[4],
                                        const uint32_t b[2]) {
    asm volatile(
        "mma.sync.aligned.m16n8k16.row.col.f32.f16.f16.f32 "
        "{%0,%1,%2,%3}, {%4,%5,%6,%7}, {%8,%9}, {%0,%1,%2,%3};"
        : "+f"(c[0]), "+f"(c[1]), "+f"(c[2]), "+f"(c[3])
        : "r"(a[0]), "r"(a[1]), "r"(a[2]), "r"(a[3]), "r"(b[0]), "r"(b[1]));
}

// Exact 2-way fp16 split of a pre-scaled value
__device__ __forceinline__ void split2(float v, __half& s0, __half& s1) {
    s0 = __float2half_rn(v);
    s1 = __float2half_rn(v - __half2float(s0));
}

// Monotone float->u32 map; key packs (value, 511-col) for first-max argmax
__device__ __forceinline__ u64 amax_key(float v, int col) {
    uint32_t u = __float_as_uint(v);
    uint32_t mu = (u & 0x80000000u) ? ~u : (u | 0x80000000u);
    return ((u64)mu << 32) | (uint32_t)(511 - col);
}

// Block-scope producer/consumer sync primitives (counters in L2).
__device__ __forceinline__ void cnt_signal(unsigned* c) {
    // all CTA threads done with their writes
    __syncthreads();
    if (threadIdx.x == 0) {
        __threadfence();           // release: writes visible before count
        atomicAdd(c, 1u);
    }
}

__device__ __forceinline__ void cnt_wait16(unsigned* c) {
    if (threadIdx.x == 0) {
        while (atomicAdd(c, 0u) < 16u) {}
        __threadfence();           // acquire: producer writes now visible
    }
    __syncthreads();
}

// ---------------------------------------------------------------------------
// Prep kernels
// ---------------------------------------------------------------------------
__global__ void prep_gates(const float* __restrict__ Wih, const float* __restrict__ Whh,
                           const float* __restrict__ bih, const float* __restrict__ bhh) {
    int idx = blockIdx.x * blockDim.x + threadIdx.x;    // [0, G4H*HID)
    int n = idx >> 9;
    int k = idx & 511;
    int orig = ((n & 3) << 9) + (n >> 2);               // interleave i,f,g,o per j
    split2(32.0f * Wih[(size_t)orig * 512 + k], g_Wih[0][idx], g_Wih[1][idx]);
    split2(32.0f * Whh[(size_t)orig * 512 + k], g_Whh[0][idx], g_Whh[1][idx]);
    if (k == 0) g_bias[n] = bih[orig] + bhh[orig];
}

__global__ void prep_out(const float* __restrict__ Wout, const float* __restrict__ emb) {
    int idx = blockIdx.x * blockDim.x + threadIdx.x;    // [0, VOCAB*HID)
    split2(32.0f * Wout[idx], g_Wo[0][idx], g_Wo[1][idx]);
    split2(16.0f * emb[idx], g_emb[0][idx], g_emb[1][idx]);
}

__global__ void init_state_tc(const float* __restrict__ ench,
                              const float* __restrict__ encc) {
    int idx = blockIdx.x * blockDim.x + threadIdx.x;    // [0, BATCH*HID)
    g_c[idx] = encc[idx];
    split2(16.0f * ench[idx], g_hs[0][0][idx], g_hs[0][1][idx]);
    if ((idx & 511) == 0) g_amax[1][idx >> 9] = 511ull;  // decodes to SOS token 0
    if (idx < T_STEPS * 8) {                             // reset dependency counters
        (&g_hcnt[0][0])[idx] = 0u;
        (&g_acnt[0][0])[idx] = 0u;
    }
}

// ---------------------------------------------------------------------------
// 128x128 main loop (K=512 in 8 chunks of 64), 256 threads, 8 warps (2Mx4N)
// Warp tile 64x32.  smem: double buffer of 4 tiles x 16KB (2 A splits, 2 B).
// Split products (0,0),(0,1),(1,0); one A-split live at a time.
// (Round-12-proven configuration.)
// ---------------------------------------------------------------------------
#define TILE128   16384
#define BUF128    (4 * TILE128)        // 65536
#define SMEM128   (2 * BUF128 + 1024)

__device__ __forceinline__ void load128(uint32_t bufb, int tid,
                                        const __half* const srcs[4], int koff) {
#pragma unroll
    for (int i = 0; i < 16; i++) {
        int t = i >> 2;
        int u = tid + (i & 3) * 256;
        int row = u >> 3;
        int cb = u & 7;
        cp16(bufb + (t << 14) + SWZ(row * 128 + cb * 16),
             srcs[t] + (size_t)row * 512 + koff + cb * 8);
    }
    asm volatile("cp.async.commit_group;" ::: "memory");
}

__device__ __forceinline__ void mainloop128(uint32_t smem, int tid,
                                            const __half* const srcs[4],
                                            float C[4][4][4]) {
    const int l = tid & 31, wid = tid >> 5;
    const int wm = wid >> 2, wn = wid & 3;

    const int a_row = l & 15;
    const int a_cb  = (l >> 4) << 4;
    const int b_row = (((l >> 4) & 1) << 3) + (l & 7);
    const int b_cb  = ((l >> 3) & 1) << 4;

    load128(smem, tid, srcs, 0);

#pragma unroll 1
    for (int ch = 0; ch < 8; ch++) {
        uint32_t cur = smem + (ch & 1) * BUF128;
        if (ch < 7) {
            load128(smem + ((ch + 1) & 1) * BUF128, tid, srcs, (ch + 1) * 64);
            asm volatile("cp.async.wait_group 1;" ::: "memory");
        } else {
            asm volatile("cp.async.wait_group 0;" ::: "memory");
        }
        __syncthreads();

#pragma unroll
        for (int ks = 0; ks < 4; ks++) {
            uint32_t B[2][4][2];
#pragma unroll
            for (int s = 0; s < 2; s++) {
#pragma unroll
                for (int nh = 0; nh < 2; nh++) {
                    uint32_t ad = cur + ((2 + s) << 14) +
                        SWZ((wn * 32 + nh * 16 + b_row) * 128 + ks * 32 + b_cb);
                    uint32_t r0, r1, r2, r3;
                    ldsm4(r0, r1, r2, r3, ad);
                    B[s][nh * 2][0] = r0; B[s][nh * 2][1] = r1;
                    B[s][nh * 2 + 1][0] = r2; B[s][nh * 2 + 1][1] = r3;
                }
            }
#pragma unroll
            for (int sa = 0; sa < 2; sa++) {
                uint32_t A[4][4];
#pragma unroll
                for (int mf = 0; mf < 4; mf++) {
                    uint32_t ad = cur + (sa << 14) +
                        SWZ((wm * 64 + mf * 16 + a_row) * 128 + ks * 32 + a_cb);
                    ldsm4(A[mf][0], A[mf][1], A[mf][2], A[mf][3], ad);
                }
#pragma unroll
                for (int sb = 0; sb < 2 - sa; sb++) {
#pragma unroll
                    for (int mf = 0; mf < 4; mf++)
#pragma unroll
                        for (int nf = 0; nf < 4; nf++)
                            mma_f16(C[mf][nf], A[mf], B[sb][nf]);
                }
            }
        }
        __syncthreads();
    }
}

// ---------------------------------------------------------------------------
// prep_E: E = emb @ W_ih^T + bias  (M=512, N=2048, K=512), grid (16, 4)
// ---------------------------------------------------------------------------
__global__ __launch_bounds__(256, 1) void prep_E_kernel() {
    extern __shared__ char dsm[];
    uint32_t smem = (smem_u32(dsm) + 1023) & ~1023u;
    int tid = threadIdx.x;
    int l = tid & 31, wid = tid >> 5;
    int wm = wid >> 2, wn = wid & 3, tg = l & 3;
    int n0 = blockIdx.x * 128, m0 = blockIdx.y * 128;

    const __half* srcs[4] = {
        g_emb[0] + (size_t)m0 * 512, g_emb[1] + (size_t)m0 * 512,
        g_Wih[0] + (size_t)n0 * 512, g_Wih[1] + (size_t)n0 * 512};

    float C[4][4][4] = {};
    mainloop128(smem, tid, srcs, C);

#pragma unroll
    for (int mf = 0; mf < 4; mf++)
#pragma unroll
        for (int nf = 0; nf < 4; nf++) {
            int n = n0 + wn * 32 + nf * 8 + tg * 2;
#pragma unroll
            for (int rh = 0; rh < 2; rh++) {
                int m = m0 + wm * 64 + mf * 16 + (l >> 2) + rh * 8;
                float2 v = make_float2(
                    C[mf][nf][rh * 2 + 0] * INV512 + g_bias[n],
                    C[mf][nf][rh * 2 + 1] * INV512 + g_bias[n + 1]);
                *(float2*)&g_E[(size_t)m * G4H + n] = v;
            }
        }
}

// ---------------------------------------------------------------------------
// Logits tile helpers (64x64 tile inside the persistent kernel)
// ---------------------------------------------------------------------------
#define TILE64   8192
#define BUF64    (4 * TILE64)          // 32768

__device__ __forceinline__ void load64(uint32_t bufb, int tid,
                                       const __half* const srcs[4], int koff) {
#pragma unroll
    for (int i = 0; i < 8; i++) {
        int t = i >> 1;
        int u = tid + (i & 1) * 256;
        int row = u >> 3;
        int cb = u & 7;
        cp16(bufb + (t << 13) + SWZ(row * 128 + cb * 16),
             srcs[t] + (size_t)row * 512 + koff + cb * 8);
    }
    asm volatile("cp.async.commit_group;" ::: "memory");
}

// ---------------------------------------------------------------------------
// Persistent step kernel with fine-grained per-m-block dependency counters.
// grid = 128 CTAs x 256 threads, occ 1 each => all co-resident (wave 1).
// CTA bid: gates tile (gm0=(bid>>4)*128, gn0=(bid&15)*128);
//          logits tile (lm0=(bid>>3)*64,  ln0=(bid&7)*64).
// Both m-blocks equal bid>>4, so each CTA waits on its own block counters.
// ---------------------------------------------------------------------------
__global__ __launch_bounds__(256, 1) void step_persistent(
    const float* __restrict__ bo, float* __restrict__ out) {
    extern __shared__ char dsm[];
    uint32_t smem = (smem_u32(dsm) + 1023) & ~1023u;
    int tid = threadIdx.x;
    int bid = blockIdx.x;
    int l = tid & 31, wid = tid >> 5;
    int wm = wid >> 2, wn = wid & 3, tg = l & 3;

    const int gn0 = (bid & 15) * 128;
    const int gm0 = (bid >> 4) * 128;
    const int ln0 = (bid & 7) * 64;
    const int lm0 = (bid >> 3) * 64;
    const int mb  = bid >> 4;            // shared m-block index

    const int a_row = l & 15;
    const int a_cb  = (l >> 4) << 4;
    const int b_row = (((l >> 4) & 1) << 3) + (l & 7);
    const int b_cb  = ((l >> 3) & 1) << 4;

#pragma unroll 1
    for (int t = 0; t < T_STEPS; t++) {
        int rd = t & 1;
        int wr = rd ^ 1;

        // ---------------- gates phase ----------------
        // Wait for this m-block's argmax keys from the previous step's logits.
        if (t > 0) cnt_wait16(&g_acnt[t - 1][mb]);

        int tok8[4][2];
#pragma unroll
        for (int mf = 0; mf < 4; mf++)
#pragma unroll
            for (int rh = 0; rh < 2; rh++) {
                int m = gm0 + wm * 64 + mf * 16 + (l >> 2) + rh * 8;
                tok8[mf][rh] = 511 - (int)(g_amax[wr][m] & 0x3ffull);
            }

        if (tid < 128) g_amax[rd][gm0 + tid] = 0ull;  // clear for this step

        {
            const __half* srcs[4] = {
                g_hs[rd][0] + (size_t)gm0 * 512, g_hs[rd][1] + (size_t)gm0 * 512,
                g_Whh[0] + (size_t)gn0 * 512, g_Whh[1] + (size_t)gn0 * 512};

            float C[4][4][4] = {};
            mainloop128(smem, tid, srcs, C);

            // Epilogue: even-tg lane holds (i,f); partner (tg^1) holds (g,o).
#pragma unroll
            for (int mf = 0; mf < 4; mf++)
#pragma unroll
                for (int rh = 0; rh < 2; rh++) {
                    int m = gm0 + wm * 64 + mf * 16 + (l >> 2) + rh * 8;
                    const float* Erow = g_E + (size_t)tok8[mf][rh] * G4H;
#pragma unroll
                    for (int nf = 0; nf < 4; nf++) {
                        float own0 = C[mf][nf][rh * 2 + 0];
                        float own1 = C[mf][nf][rh * 2 + 1];
                        float p0 = __shfl_xor_sync(0xffffffffu, own0, 1);
                        float p1 = __shfl_xor_sync(0xffffffffu, own1, 1);
                        if (!(tg & 1)) {
                            int n = gn0 + wn * 32 + nf * 8 + tg * 2;  // = 4*j
                            int j = n >> 2;
                            float4 e = *(const float4*)&Erow[n];
                            float gi = own0 * INV512 + e.x;
                            float gf = own1 * INV512 + e.y;
                            float gg = p0 * INV512 + e.z;
                            float go = p1 * INV512 + e.w;
                            float is = 1.f / (1.f + expf(-gi));
                            float fs = 1.f / (1.f + expf(-gf));
                            float os = 1.f / (1.f + expf(-go));
                            size_t hx = (size_t)m * HID + j;
                            float cn = fs * g_c[hx] + is * tanhf(gg);
                            g_c[hx] = cn;
                            float hn = os * tanhf(cn);
                            split2(16.0f * hn, g_hs[wr][0][hx], g_hs[wr][1][hx]);
                        }
                    }
                }
        }

        cnt_signal(&g_hcnt[t][mb]);   // this CTA's h columns for block mb ready

        // ---------------- logits phase ----------------
        // Wait for all 16 gates CTAs of this m-block (full h rows + amax clear).
        cnt_wait16(&g_hcnt[t][mb]);

        {
            float* out_t = out + (size_t)t * BATCH * VOCAB;
            const __half* srcs[4] = {
                g_hs[wr][0] + (size_t)lm0 * 512, g_hs[wr][1] + (size_t)lm0 * 512,
                g_Wo[0] + (size_t)ln0 * 512, g_Wo[1] + (size_t)ln0 * 512};

            float C[2][2][4] = {};

            load64(smem, tid, srcs, 0);
#pragma unroll 1
            for (int ch = 0; ch < 8; ch++) {
                uint32_t cur = smem + (ch & 1) * BUF64;
                if (ch < 7) {
                    load64(smem + ((ch + 1) & 1) * BUF64, tid, srcs, (ch + 1) * 64);
                    asm volatile("cp.async.wait_group 1;" ::: "memory");
                } else {
                    asm volatile("cp.async.wait_group 0;" ::: "memory");
                }
                __syncthreads();

#pragma unroll
                for (int ks = 0; ks < 4; ks++) {
                    uint32_t B[2][2][2];
#pragma unroll
                    for (int s = 0; s < 2; s++) {
                        uint32_t ad = cur + ((2 + s) << 13) +
                            SWZ((wn * 16 + b_row) * 128 + ks * 32 + b_cb);
                        uint32_t r0, r1, r2, r3;
                        ldsm4(r0, r1, r2, r3, ad);
                        B[s][0][0] = r0; B[s][0][1] = r1;
                        B[s][1][0] = r2; B[s][1][1] = r3;
                    }
#pragma unroll
                    for (int sa = 0; sa < 2; sa++) {
                        uint32_t A[2][4];
#pragma unroll
                        for (int mf = 0; mf < 2; mf++) {
                            uint32_t ad = cur + (sa << 13) +
                                SWZ((wm * 32 + mf * 16 + a_row) * 128 + ks * 32 + a_cb);
                            ldsm4(A[mf][0], A[mf][1], A[mf][2], A[mf][3], ad);
                        }
#pragma unroll
                        for (int sb = 0; sb < 2 - sa; sb++) {
#pragma unroll
                            for (int mf = 0; mf < 2; mf++)
#pragma unroll
                                for (int nf = 0; nf < 2; nf++)
                                    mma_f16(C[mf][nf], A[mf], B[sb][nf]);
                        }
                    }
                }
                __syncthreads();
            }

#pragma unroll
            for (int mf = 0; mf < 2; mf++)
#pragma unroll
                for (int rh = 0; rh < 2; rh++) {
                    int m = lm0 + wm * 32 + mf * 16 + (l >> 2) + rh * 8;
                    u64 best = 0ull;
#pragma unroll
                    for (int nf = 0; nf < 2; nf++) {
                        int n = ln0 + wn * 16 + nf * 8 + tg * 2;
                        float v0 = C[mf][nf][rh * 2 + 0] * INV512 + bo[n];
                        float v1 = C[mf][nf][rh * 2 + 1] * INV512 + bo[n + 1];
                        *(float2*)&out_t[(size_t)m * VOCAB + n] = make_float2(v0, v1);
                        u64 k0 = amax_key(v0, n), k1 = amax_key(v1, n + 1);
                        if (k0 > best) best = k0;
                        if (k1 > best) best = k1;
                    }
                    u64 o1 = __shfl_xor_sync(0xffffffffu, best, 1);
                    if (o1 > best) best = o1;
                    u64 o2 = __shfl_xor_sync(0xffffffffu, best, 2);
                    if (o2 > best) best = o2;
                    if (tg == 0) atomicMax(&g_amax[rd][m], best);
                }
        }

        cnt_signal(&g_acnt[t][mb]);   // argmax contribution for block mb done
    }
}

// ---------------------------------------------------------------------------
// Launch
// ---------------------------------------------------------------------------
extern "C" void kernel_launch(void* const* d_in, const int* in_sizes, int n_in,
                              void* d_out, int out_size) {
    const float* enc_h = (const float*)d_in[2];
    const float* enc_c = (const float*)d_in[3];
    const float* emb   = (const float*)d_in[4];
    const float* W_ih  = (const float*)d_in[5];
    const float* W_hh  = (const float*)d_in[6];
    const float* b_ih  = (const float*)d_in[7];
    const float* b_hh  = (const float*)d_in[8];
    const float* W_out = (const float*)d_in[9];
    const float* b_out = (const float*)d_in[10];
    float* out = (float*)d_out;

    cudaFuncSetAttribute(prep_E_kernel, cudaFuncAttributeMaxDynamicSharedMemorySize, SMEM128);
    cudaFuncSetAttribute(step_persistent, cudaFuncAttributeMaxDynamicSharedMemorySize, SMEM128);

    prep_gates<<<(G4H * HID) / 256, 256>>>(W_ih, W_hh, b_ih, b_hh);
    prep_out<<<(VOCAB * HID) / 256, 256>>>(W_out, emb);
    init_state_tc<<<(BATCH * HID) / 256, 256>>>(enc_h, enc_c);
    prep_E_kernel<<<dim3(16, 4), 256, SMEM128>>>();

    step_persistent<<<NCTA, 256, SMEM128>>>(b_out, out);
}

// round 17
// speedup vs baseline: 1.4811x; 1.2297x over previous
#include <cuda_runtime.h>
#include <cuda_fp16.h>
#include <math.h>
#include <stdint.h>

#define T_STEPS 64
#define BATCH   1024
#define HID     512
#define VOCAB   512
#define G4H     2048
#define NCTA    128

typedef unsigned long long u64;

// ---------------------------------------------------------------------------
// Device-global scratch (allocation-free)
// A-side operands (h, emb) pre-scaled by 16; B-side weights by 32.
// GEMM accumulators therefore carry 512x; epilogues multiply by 1/512.
// ---------------------------------------------------------------------------
__device__ float  g_c[BATCH * HID];            // cell state fp32
__device__ __half g_hs[2][2][BATCH * HID];     // 16*h 2-way fp16 splits, ping-pong
__device__ __half g_Wih[2][G4H * HID];         // 32*W_ih splits (gate-interleaved)
__device__ __half g_Whh[2][G4H * HID];         // 32*W_hh splits (gate-interleaved)
__device__ __half g_Wo[2][VOCAB * HID];        // 32*W_out splits
__device__ __half g_emb[2][VOCAB * HID];       // 16*embedding splits
__device__ float  g_bias[G4H];                 // gate-interleaved b_ih+b_hh
__device__ float  g_E[VOCAB * G4H];            // emb @ W_ih^T + bias (fp32, true scale)
__device__ u64    g_amax[2][BATCH];            // packed (mapped logit, 511-col)
__device__ unsigned g_hcnt[T_STEPS][8];        // per-(step, m-block) h-ready count
__device__ unsigned g_acnt[T_STEPS][8];        // per-(step, m-block) amax-ready count

#define INV512 (1.0f / 512.0f)

// ---------------------------------------------------------------------------
// Helpers
// ---------------------------------------------------------------------------
__device__ __forceinline__ uint32_t smem_u32(const void* p) {
    uint32_t a;
    asm("{ .reg .u64 t; cvta.to.shared.u64 t, %1; cvt.u32.u64 %0, t; }"
        : "=r"(a) : "l"(p));
    return a;
}

#define SWZ(x) ((x) ^ (((x) >> 3) & 0x70))

__device__ __forceinline__ void cp16(uint32_t dst, const void* src) {
    asm volatile("cp.async.cg.shared.global [%0], [%1], 16;" :: "r"(dst), "l"(src));
}

__device__ __forceinline__ void ldsm4(uint32_t& r0, uint32_t& r1,
                                      uint32_t& r2, uint32_t& r3, uint32_t addr) {
    asm volatile("ldmatrix.sync.aligned.m8n8.x4.shared.b16 {%0,%1,%2,%3}, [%4];"
                 : "=r"(r0), "=r"(r1), "=r"(r2), "=r"(r3) : "r"(addr));
}

__device__ __forceinline__ void mma_f16(float c[4], const uint32_t a[4],
                                        const uint32_t b[2]) {
    asm volatile(
        "mma.sync.aligned.m16n8k16.row.col.f32.f16.f16.f32 "
        "{%0,%1,%2,%3}, {%4,%5,%6,%7}, {%8,%9}, {%0,%1,%2,%3};"
        : "+f"(c[0]), "+f"(c[1]), "+f"(c[2]), "+f"(c[3])
        : "r"(a[0]), "r"(a[1]), "r"(a[2]), "r"(a[3]), "r"(b[0]), "r"(b[1]));
}

// Exact 2-way fp16 split of a pre-scaled value
__device__ __forceinline__ void split2(float v, __half& s0, __half& s1) {
    s0 = __float2half_rn(v);
    s1 = __float2half_rn(v - __half2float(s0));
}

// Monotone float->u32 map; key packs (value, 511-col) for first-max argmax
__device__ __forceinline__ u64 amax_key(float v, int col) {
    uint32_t u = __float_as_uint(v);
    uint32_t mu = (u & 0x80000000u) ? ~u : (u | 0x80000000u);
    return ((u64)mu << 32) | (uint32_t)(511 - col);
}

// Block-scope producer/consumer sync primitives (counters in L2).
__device__ __forceinline__ void cnt_signal(unsigned* c) {
    __syncthreads();
    if (threadIdx.x == 0) {
        __threadfence();           // release
        atomicAdd(c, 1u);
    }
}

__device__ __forceinline__ void cnt_wait16(unsigned* c) {
    if (threadIdx.x == 0) {
        while (atomicAdd(c, 0u) < 16u) {}
        __threadfence();           // acquire
    }
    __syncthreads();
}

// ---------------------------------------------------------------------------
// Prep kernels
// ---------------------------------------------------------------------------
__global__ void prep_gates(const float* __restrict__ Wih, const float* __restrict__ Whh,
                           const float* __restrict__ bih, const float* __restrict__ bhh) {
    int idx = blockIdx.x * blockDim.x + threadIdx.x;    // [0, G4H*HID)
    int n = idx >> 9;
    int k = idx & 511;
    int orig = ((n & 3) << 9) + (n >> 2);               // interleave i,f,g,o per j
    split2(32.0f * Wih[(size_t)orig * 512 + k], g_Wih[0][idx], g_Wih[1][idx]);
    split2(32.0f * Whh[(size_t)orig * 512 + k], g_Whh[0][idx], g_Whh[1][idx]);
    if (k == 0) g_bias[n] = bih[orig] + bhh[orig];
}

__global__ void prep_out(const float* __restrict__ Wout, const float* __restrict__ emb) {
    int idx = blockIdx.x * blockDim.x + threadIdx.x;    // [0, VOCAB*HID)
    split2(32.0f * Wout[idx], g_Wo[0][idx], g_Wo[1][idx]);
    split2(16.0f * emb[idx], g_emb[0][idx], g_emb[1][idx]);
}

__global__ void init_state_tc(const float* __restrict__ ench,
                              const float* __restrict__ encc) {
    int idx = blockIdx.x * blockDim.x + threadIdx.x;    // [0, BATCH*HID)
    g_c[idx] = encc[idx];
    split2(16.0f * ench[idx], g_hs[0][0][idx], g_hs[0][1][idx]);
    if ((idx & 511) == 0) g_amax[1][idx >> 9] = 511ull;  // decodes to SOS token 0
    if (idx < T_STEPS * 8) {
        (&g_hcnt[0][0])[idx] = 0u;
        (&g_acnt[0][0])[idx] = 0u;
    }
}

// ---------------------------------------------------------------------------
// Old-style full-load mainloop, used only by prep_E (runs once).
// ---------------------------------------------------------------------------
#define TILE128   16384
#define BUF128    (4 * TILE128)        // 65536
#define SMEM_PE   (2 * BUF128 + 1024)

__device__ __forceinline__ void load128(uint32_t bufb, int tid,
                                        const __half* const srcs[4], int koff) {
#pragma unroll
    for (int i = 0; i < 16; i++) {
        int t = i >> 2;
        int u = tid + (i & 3) * 256;
        int row = u >> 3;
        int cb = u & 7;
        cp16(bufb + (t << 14) + SWZ(row * 128 + cb * 16),
             srcs[t] + (size_t)row * 512 + koff + cb * 8);
    }
    asm volatile("cp.async.commit_group;" ::: "memory");
}

__device__ __forceinline__ void mma_block128(uint32_t curA, uint32_t curB,
                                             int a_row, int a_cb, int b_row, int b_cb,
                                             int wm, int wn, float C[4][4][4]) {
#pragma unroll
    for (int ks = 0; ks < 4; ks++) {
        uint32_t B[2][4][2];
#pragma unroll
        for (int s = 0; s < 2; s++) {
#pragma unroll
            for (int nh = 0; nh < 2; nh++) {
                uint32_t ad = curB + (s << 14) +
                    SWZ((wn * 32 + nh * 16 + b_row) * 128 + ks * 32 + b_cb);
                uint32_t r0, r1, r2, r3;
                ldsm4(r0, r1, r2, r3, ad);
                B[s][nh * 2][0] = r0; B[s][nh * 2][1] = r1;
                B[s][nh * 2 + 1][0] = r2; B[s][nh * 2 + 1][1] = r3;
            }
        }
#pragma unroll
        for (int sa = 0; sa < 2; sa++) {
            uint32_t A[4][4];
#pragma unroll
            for (int mf = 0; mf < 4; mf++) {
                uint32_t ad = curA + (sa << 14) +
                    SWZ((wm * 64 + mf * 16 + a_row) * 128 + ks * 32 + a_cb);
                ldsm4(A[mf][0], A[mf][1], A[mf][2], A[mf][3], ad);
            }
#pragma unroll
            for (int sb = 0; sb < 2 - sa; sb++)
#pragma unroll
                for (int mf = 0; mf < 4; mf++)
#pragma unroll
                    for (int nf = 0; nf < 4; nf++)
                        mma_f16(C[mf][nf], A[mf], B[sb][nf]);
        }
    }
}

__global__ __launch_bounds__(256, 1) void prep_E_kernel() {
    extern __shared__ char dsm[];
    uint32_t smem = (smem_u32(dsm) + 1023) & ~1023u;
    int tid = threadIdx.x;
    int l = tid & 31, wid = tid >> 5;
    int wm = wid >> 2, wn = wid & 3, tg = l & 3;
    int n0 = blockIdx.x * 128, m0 = blockIdx.y * 128;

    const __half* srcs[4] = {
        g_emb[0] + (size_t)m0 * 512, g_emb[1] + (size_t)m0 * 512,
        g_Wih[0] + (size_t)n0 * 512, g_Wih[1] + (size_t)n0 * 512};

    const int a_row = l & 15;
    const int a_cb  = (l >> 4) << 4;
    const int b_row = (((l >> 4) & 1) << 3) + (l & 7);
    const int b_cb  = ((l >> 3) & 1) << 4;

    float C[4][4][4] = {};
    load128(smem, tid, srcs, 0);
#pragma unroll 1
    for (int ch = 0; ch < 8; ch++) {
        uint32_t cur = smem + (ch & 1) * BUF128;
        if (ch < 7) {
            load128(smem + ((ch + 1) & 1) * BUF128, tid, srcs, (ch + 1) * 64);
            asm volatile("cp.async.wait_group 1;" ::: "memory");
        } else {
            asm volatile("cp.async.wait_group 0;" ::: "memory");
        }
        __syncthreads();
        mma_block128(cur, cur + 32768, a_row, a_cb, b_row, b_cb, wm, wn, C);
        __syncthreads();
    }

#pragma unroll
    for (int mf = 0; mf < 4; mf++)
#pragma unroll
        for (int nf = 0; nf < 4; nf++) {
            int n = n0 + wn * 32 + nf * 8 + tg * 2;
#pragma unroll
            for (int rh = 0; rh < 2; rh++) {
                int m = m0 + wm * 64 + mf * 16 + (l >> 2) + rh * 8;
                float2 v = make_float2(
                    C[mf][nf][rh * 2 + 0] * INV512 + g_bias[n],
                    C[mf][nf][rh * 2 + 1] * INV512 + g_bias[n + 1]);
                *(float2*)&g_E[(size_t)m * G4H + n] = v;
            }
        }
}

// ---------------------------------------------------------------------------
// Persistent kernel smem layout:
//   [0, 64K)      resident gates-B: W_hh chunks 0..1, tile(ch,s) at (ch*2+s)*16K
//   [64K, 96K)    resident logits-B: W_o chunks 0..1, tile(ch,s) at (ch*2+s)*8K
//   [96K, 224K)   dynamic stages: gates 2 x 64K (A@+0,+16K; B@+32K,+48K)
//                 logits overlays same region: 2 x 32K (A@+0,+8K; B@+16K,+24K)
// ---------------------------------------------------------------------------
#define GBRES_OFF 0
#define LBRES_OFF 65536
#define DYN_OFF   98304
#define GSTG      65536
#define LSTG      32768
#define SMEM_PS   (98304 + 131072 + 1024)   // 230400

// gates A-only load (2 tiles of 16K): 8 cp16/thread
__device__ __forceinline__ void g_loadA(uint32_t dst, int tid,
                                        const __half* const sA[2], int koff) {
#pragma unroll
    for (int i = 0; i < 8; i++) {
        int t = i >> 2;
        int u = tid + (i & 3) * 256;
        int row = u >> 3, cb = u & 7;
        cp16(dst + t * 16384 + SWZ(row * 128 + cb * 16),
             sA[t] + (size_t)row * 512 + koff + cb * 8);
    }
    asm volatile("cp.async.commit_group;" ::: "memory");
}

// gates full load (A 2 tiles + B 2 tiles): 16 cp16/thread
__device__ __forceinline__ void g_loadFull(uint32_t dst, int tid,
                                           const __half* const sA[2],
                                           const __half* const sB[2], int koff) {
#pragma unroll
    for (int i = 0; i < 16; i++) {
        int t = i >> 2;
        int u = tid + (i & 3) * 256;
        int row = u >> 3, cb = u & 7;
        const __half* s = (t < 2) ? sA[t] : sB[t - 2];
        cp16(dst + t * 16384 + SWZ(row * 128 + cb * 16),
             s + (size_t)row * 512 + koff + cb * 8);
    }
    asm volatile("cp.async.commit_group;" ::: "memory");
}

// logits A-only load (2 tiles of 8K): 4 cp16/thread
__device__ __forceinline__ void l_loadA(uint32_t dst, int tid,
                                        const __half* const sA[2], int koff) {
#pragma unroll
    for (int i = 0; i < 4; i++) {
        int t = i >> 1;
        int u = tid + (i & 1) * 256;
        int row = u >> 3, cb = u & 7;
        cp16(dst + t * 8192 + SWZ(row * 128 + cb * 16),
             sA[t] + (size_t)row * 512 + koff + cb * 8);
    }
    asm volatile("cp.async.commit_group;" ::: "memory");
}

// logits full load: 8 cp16/thread
__device__ __forceinline__ void l_loadFull(uint32_t dst, int tid,
                                           const __half* const sA[2],
                                           const __half* const sB[2], int koff) {
#pragma unroll
    for (int i = 0; i < 8; i++) {
        int t = i >> 1;
        int u = tid + (i & 1) * 256;
        int row = u >> 3, cb = u & 7;
        const __half* s = (t < 2) ? sA[t] : sB[t - 2];
        cp16(dst + t * 8192 + SWZ(row * 128 + cb * 16),
             s + (size_t)row * 512 + koff + cb * 8);
    }
    asm volatile("cp.async.commit_group;" ::: "memory");
}

__global__ __launch_bounds__(256, 1) void step_persistent(
    const float* __restrict__ bo, float* __restrict__ out) {
    extern __shared__ char dsm[];
    uint32_t S = (smem_u32(dsm) + 1023) & ~1023u;
    int tid = threadIdx.x;
    int bid = blockIdx.x;
    int l = tid & 31, wid = tid >> 5;
    int wm = wid >> 2, wn = wid & 3, tg = l & 3;

    const int gn0 = (bid & 15) * 128;
    const int gm0 = (bid >> 4) * 128;
    const int ln0 = (bid & 7) * 64;
    const int lm0 = (bid >> 3) * 64;
    const int mb  = bid >> 4;

    const int a_row = l & 15;
    const int a_cb  = (l >> 4) << 4;
    const int b_row = (((l >> 4) & 1) << 3) + (l & 7);
    const int b_cb  = ((l >> 3) & 1) << 4;
    const bool odd  = (l & 1);

    const __half* gA[2];   // per-step (set in loop)
    const __half* gB[2] = {g_Whh[0] + (size_t)gn0 * 512, g_Whh[1] + (size_t)gn0 * 512};
    const __half* lB[2] = {g_Wo[0] + (size_t)ln0 * 512, g_Wo[1] + (size_t)ln0 * 512};

    // ---- one-time resident weight preload (chunks 0..1 of B panels) ----
#pragma unroll
    for (int i = 0; i < 16; i++) {          // gates B: 4 tiles x 16K
        int t = i >> 2;
        int ch = t >> 1, s = t & 1;
        int u = tid + (i & 3) * 256;
        int row = u >> 3, cb = u & 7;
        cp16(S + GBRES_OFF + t * 16384 + SWZ(row * 128 + cb * 16),
             gB[s] + (size_t)row * 512 + ch * 64 + cb * 8);
    }
#pragma unroll
    for (int i = 0; i < 8; i++) {           // logits B: 4 tiles x 8K
        int t = i >> 1;
        int ch = t >> 1, s = t & 1;
        int u = tid + (i & 1) * 256;
        int row = u >> 3, cb = u & 7;
        cp16(S + LBRES_OFF + t * 8192 + SWZ(row * 128 + cb * 16),
             lB[s] + (size_t)row * 512 + ch * 64 + cb * 8);
    }
    asm volatile("cp.async.commit_group;" ::: "memory");
    asm volatile("cp.async.wait_group 0;" ::: "memory");
    __syncthreads();

    const uint32_t dyn = S + DYN_OFF;

#pragma unroll 1
    for (int t = 0; t < T_STEPS; t++) {
        int rd = t & 1;
        int wr = rd ^ 1;

        // ---------------- gates phase ----------------
        if (t > 0) cnt_wait16(&g_acnt[t - 1][mb]);

        int tok8[4][2];
#pragma unroll
        for (int mf = 0; mf < 4; mf++)
#pragma unroll
            for (int rh = 0; rh < 2; rh++) {
                int m = gm0 + wm * 64 + mf * 16 + (l >> 2) + rh * 8;
                tok8[mf][rh] = 511 - (int)(g_amax[wr][m] & 0x3ffull);
            }

        if (tid < 128) g_amax[rd][gm0 + tid] = 0ull;

        gA[0] = g_hs[rd][0] + (size_t)gm0 * 512;
        gA[1] = g_hs[rd][1] + (size_t)gm0 * 512;

        float C[4][4][4] = {};
        g_loadA(dyn, tid, gA, 0);                 // ch0: A only (B resident)
#pragma unroll 1
        for (int ch = 0; ch < 8; ch++) {
            uint32_t curA = dyn + (ch & 1) * GSTG;
            uint32_t curB = (ch < 2) ? (S + GBRES_OFF + ch * 32768)
                                     : (curA + 32768);
            if (ch < 7) {
                uint32_t nb = dyn + ((ch + 1) & 1) * GSTG;
                if (ch == 0) g_loadA(nb, tid, gA, 64);
                else         g_loadFull(nb, tid, gA, gB, (ch + 1) * 64);
                asm volatile("cp.async.wait_group 1;" ::: "memory");
            } else {
                asm volatile("cp.async.wait_group 0;" ::: "memory");
            }
            __syncthreads();
            mma_block128(curA, curB, a_row, a_cb, b_row, b_cb, wm, wn, C);
            __syncthreads();
        }

        // All-lane LSTM epilogue: lane pair (even,odd) handles nf pair per iter.
#pragma unroll
        for (int mf = 0; mf < 4; mf++)
#pragma unroll
            for (int rh = 0; rh < 2; rh++) {
                int m = gm0 + wm * 64 + mf * 16 + (l >> 2) + rh * 8;
                const float* Erow = g_E + (size_t)tok8[mf][rh] * G4H;
#pragma unroll
                for (int np = 0; np < 2; np++) {
                    int nfa = np * 2, nfb = np * 2 + 1;
                    float sv0 = odd ? C[mf][nfa][rh * 2 + 0] : C[mf][nfb][rh * 2 + 0];
                    float sv1 = odd ? C[mf][nfa][rh * 2 + 1] : C[mf][nfb][rh * 2 + 1];
                    float p0 = __shfl_xor_sync(0xffffffffu, sv0, 1);
                    float p1 = __shfl_xor_sync(0xffffffffu, sv1, 1);
                    float fi = odd ? p0 : C[mf][nfa][rh * 2 + 0];
                    float ff = odd ? p1 : C[mf][nfa][rh * 2 + 1];
                    float fg = odd ? C[mf][nfb][rh * 2 + 0] : p0;
                    float fo = odd ? C[mf][nfb][rh * 2 + 1] : p1;
                    int nf = odd ? nfb : nfa;
                    int n = gn0 + wn * 32 + nf * 8 + (tg & 2) * 2;   // = 4*j
                    int j = n >> 2;
                    float4 e = *(const float4*)&Erow[n];
                    float gi = fi * INV512 + e.x;
                    float gf = ff * INV512 + e.y;
                    float gg = fg * INV512 + e.z;
                    float go = fo * INV512 + e.w;
                    float is = 1.f / (1.f + expf(-gi));
                    float fs = 1.f / (1.f + expf(-gf));
                    float os = 1.f / (1.f + expf(-go));
                    size_t hx = (size_t)m * HID + j;
                    float cn = fs * g_c[hx] + is * tanhf(gg);
                    g_c[hx] = cn;
                    float hn = os * tanhf(cn);
                    split2(16.0f * hn, g_hs[wr][0][hx], g_hs[wr][1][hx]);
                }
            }

        cnt_signal(&g_hcnt[t][mb]);

        // ---------------- logits phase ----------------
        cnt_wait16(&g_hcnt[t][mb]);

        {
            float* out_t = out + (size_t)t * BATCH * VOCAB;
            const __half* lA[2] = {
                g_hs[wr][0] + (size_t)lm0 * 512, g_hs[wr][1] + (size_t)lm0 * 512};

            float Cl[2][2][4] = {};
            l_loadA(dyn, tid, lA, 0);             // ch0: A only (B resident)
#pragma unroll 1
            for (int ch = 0; ch < 8; ch++) {
                uint32_t curA = dyn + (ch & 1) * LSTG;
                uint32_t curB = (ch < 2) ? (S + LBRES_OFF + ch * 16384)
                                         : (curA + 16384);
                if (ch < 7) {
                    uint32_t nb = dyn + ((ch + 1) & 1) * LSTG;
                    if (ch == 0) l_loadA(nb, tid, lA, 64);
                    else         l_loadFull(nb, tid, lA, lB, (ch + 1) * 64);
                    asm volatile("cp.async.wait_group 1;" ::: "memory");
                } else {
                    asm volatile("cp.async.wait_group 0;" ::: "memory");
                }
                __syncthreads();

#pragma unroll
                for (int ks = 0; ks < 4; ks++) {
                    uint32_t B[2][2][2];
#pragma unroll
                    for (int s = 0; s < 2; s++) {
                        uint32_t ad = curB + (s << 13) +
                            SWZ((wn * 16 + b_row) * 128 + ks * 32 + b_cb);
                        uint32_t r0, r1, r2, r3;
                        ldsm4(r0, r1, r2, r3, ad);
                        B[s][0][0] = r0; B[s][0][1] = r1;
                        B[s][1][0] = r2; B[s][1][1] = r3;
                    }
#pragma unroll
                    for (int sa = 0; sa < 2; sa++) {
                        uint32_t A[2][4];
#pragma unroll
                        for (int mf = 0; mf < 2; mf++) {
                            uint32_t ad = curA + (sa << 13) +
                                SWZ((wm * 32 + mf * 16 + a_row) * 128 + ks * 32 + a_cb);
                            ldsm4(A[mf][0], A[mf][1], A[mf][2], A[mf][3], ad);
                        }
#pragma unroll
                        for (int sb = 0; sb < 2 - sa; sb++)
#pragma unroll
                            for (int mf = 0; mf < 2; mf++)
#pragma unroll
                                for (int nf = 0; nf < 2; nf++)
                                    mma_f16(Cl[mf][nf], A[mf], B[sb][nf]);
                    }
                }
                __syncthreads();
            }

#pragma unroll
            for (int mf = 0; mf < 2; mf++)
#pragma unroll
                for (int rh = 0; rh < 2; rh++) {
                    int m = lm0 + wm * 32 + mf * 16 + (l >> 2) + rh * 8;
                    u64 best = 0ull;
#pragma unroll
                    for (int nf = 0; nf < 2; nf++) {
                        int n = ln0 + wn * 16 + nf * 8 + tg * 2;
                        float v0 = Cl[mf][nf][rh * 2 + 0] * INV512 + bo[n];
                        float v1 = Cl[mf][nf][rh * 2 + 1] * INV512 + bo[n + 1];
                        *(float2*)&out_t[(size_t)m * VOCAB + n] = make_float2(v0, v1);
                        u64 k0 = amax_key(v0, n), k1 = amax_key(v1, n + 1);
                        if (k0 > best) best = k0;
                        if (k1 > best) best = k1;
                    }
                    u64 o1 = __shfl_xor_sync(0xffffffffu, best, 1);
                    if (o1 > best) best = o1;
                    u64 o2 = __shfl_xor_sync(0xffffffffu, best, 2);
                    if (o2 > best) best = o2;
                    if (tg == 0) atomicMax(&g_amax[rd][m], best);
                }
        }

        cnt_signal(&g_acnt[t][mb]);
    }
}

// ---------------------------------------------------------------------------
// Launch
// ---------------------------------------------------------------------------
extern "C" void kernel_launch(void* const* d_in, const int* in_sizes, int n_in,
                              void* d_out, int out_size) {
    const float* enc_h = (const float*)d_in[2];
    const float* enc_c = (const float*)d_in[3];
    const float* emb   = (const float*)d_in[4];
    const float* W_ih  = (const float*)d_in[5];
    const float* W_hh  = (const float*)d_in[6];
    const float* b_ih  = (const float*)d_in[7];
    const float* b_hh  = (const float*)d_in[8];
    const float* W_out = (const float*)d_in[9];
    const float* b_out = (const float*)d_in[10];
    float* out = (float*)d_out;

    cudaFuncSetAttribute(prep_E_kernel, cudaFuncAttributeMaxDynamicSharedMemorySize, SMEM_PE);
    cudaFuncSetAttribute(step_persistent, cudaFuncAttributeMaxDynamicSharedMemorySize, SMEM_PS);

    prep_gates<<<(G4H * HID) / 256, 256>>>(W_ih, W_hh, b_ih, b_hh);
    prep_out<<<(VOCAB * HID) / 256, 256>>>(W_out, emb);
    init_state_tc<<<(BATCH * HID) / 256, 256>>>(enc_h, enc_c);
    prep_E_kernel<<<dim3(16, 4), 256, SMEM_PE>>>();

    step_persistent<<<NCTA, 256, SMEM_PS>>>(b_out, out);
}